// round 6
// baseline (speedup 1.0000x reference)
#include <cuda_runtime.h>

#define IMG    64
#define OUTW   61
#define NB     256
#define NBLK   1024            // 256 images x 4 row-slices
#define NOUT   (OUTW * OUTW)

// Deterministic scratch + completion ticket (rearmed each call -> graph-replayable).
__device__ float        g_partials[NBLK];
__device__ unsigned int g_ticket = 0;

__device__ __forceinline__ float fast_sigmoid(float x)
{
    float h = 0.5f * x, t;
    asm("tanh.approx.f32 %0, %1;" : "=f"(t) : "f"(h));
    return fmaf(0.5f, t, 0.5f);      // sigmoid(x) = 0.5*tanh(x/2) + 0.5
}

__global__ void __launch_bounds__(256, 7) conv_hybrid_fused(
    const float* __restrict__ data,
    const float* __restrict__ conv_w,
    const float* __restrict__ conv_b,
    float* __restrict__ out)
{
    __shared__ float wsh[17];
    __shared__ float red[8];
    __shared__ bool  is_last;

    const int t = threadIdx.x;
    if (t < 16) wsh[t] = conv_w[t];
    if (t == 16) wsh[16] = conv_b[0];
    __syncthreads();                         // tiny: only weights

    const int b = blockIdx.x >> 2;           // image
    const int s = blockIdx.x & 3;            // row-slice
    const int nrows = (s < 3) ? 16 : 13;     // output rows in this slice

    const int r = t >> 4;                    // output row within slice
    const int g = t & 15;                    // 4-col group -> cols 4g..4g+3
    const int rc = (r < nrows) ? r : (nrows - 1);   // clamp keeps loads in-bounds

    // 4 front-batched LDG.128: rows rc..rc+3, cols 4g..4g+3. Max row index:
    // s=3 -> 48+12+3 = 63. Never OOB.
    const float* p = data + ((size_t)b << 12) + (s * 16 + rc) * IMG + (g << 2);
    const float4 A = *(const float4*)(p);
    const float4 B = *(const float4*)(p + IMG);
    const float4 C = *(const float4*)(p + 2 * IMG);
    const float4 D = *(const float4*)(p + 3 * IMG);

    const float bias = wsh[16];
    float acc0 = bias, acc1 = bias, acc2 = bias, acc3 = bias;

    // Halo cols 4g+4..4g+6 come from lane+1's float4 via shuffle. For g==15
    // (and the last lane) the shuffled values are garbage from another row /
    // clamped self — they feed only acc1..acc3, which are discarded there.
#define DO_ROW(F, wi) do {                                                  \
        const float v4 = __shfl_down_sync(0xffffffffu, (F).x, 1);           \
        const float v5 = __shfl_down_sync(0xffffffffu, (F).y, 1);           \
        const float v6 = __shfl_down_sync(0xffffffffu, (F).z, 1);           \
        const float w0 = wsh[(wi)+0], w1 = wsh[(wi)+1];                     \
        const float w2 = wsh[(wi)+2], w3 = wsh[(wi)+3];                     \
        acc0 = fmaf((F).x, w0, fmaf((F).y, w1, fmaf((F).z, w2, fmaf((F).w, w3, acc0)))); \
        acc1 = fmaf((F).y, w0, fmaf((F).z, w1, fmaf((F).w, w2, fmaf(v4,    w3, acc1)))); \
        acc2 = fmaf((F).z, w0, fmaf((F).w, w1, fmaf(v4,    w2, fmaf(v5,    w3, acc2)))); \
        acc3 = fmaf((F).w, w0, fmaf(v4,    w1, fmaf(v5,    w2, fmaf(v6,    w3, acc3)))); \
    } while (0)

    DO_ROW(A, 0);
    DO_ROW(B, 4);
    DO_ROW(C, 8);
    DO_ROW(D, 12);
#undef DO_ROW

    float lsum = 0.0f;
    if (r < nrows) {
        lsum = fast_sigmoid(acc0);                 // j = 4g, always < 61
        if (g < 15)                                // j+1..j+3 valid iff g < 15
            lsum += fast_sigmoid(acc1) + fast_sigmoid(acc2) + fast_sigmoid(acc3);
    }

    // Deterministic intra-block tree reduce.
    #pragma unroll
    for (int o = 16; o; o >>= 1)
        lsum += __shfl_xor_sync(0xffffffffu, lsum, o);
    if ((t & 31) == 0) red[t >> 5] = lsum;
    __syncthreads();

    if (t == 0) {
        float v = 0.0f;
        #pragma unroll
        for (int k = 0; k < 8; k++) v += red[k];
        g_partials[blockIdx.x] = v;
        __threadfence();                            // publish before ticket
        is_last = (atomicAdd(&g_ticket, 1u) == NBLK - 1);
    }
    __syncthreads();

    if (!is_last) return;

    // ── Last block: global reduce over 1024 partials (fixed order). ──
    if (t == 0) atomicExch(&g_ticket, 0u);          // rearm for graph replay

    float v = 0.0f;
    #pragma unroll
    for (int k = 0; k < 4; k++)
        v += g_partials[t + k * 256];
    #pragma unroll
    for (int o = 16; o; o >>= 1)
        v += __shfl_xor_sync(0xffffffffu, v, o);
    if ((t & 31) == 0) red[t >> 5] = v;
    __syncthreads();

    float total = 0.0f;
    #pragma unroll
    for (int k = 0; k < 8; k++) total += red[k];

    // Quantum term: the state stays exactly uniform under RX(theta in
    // {0, float32(pi)}) and the CX chain, so qexp = (c^2+s^2)^k - 1 and
    // c^2+s^2 == 1.0f exactly in fp32 -> qexp == 0 for every batch element.
    // Hence out[b] = 0.5 * classical_mean for all b.
    const float mean = total * (1.0f / ((float)NB * (float)NOUT));
    out[t] = 0.5f * mean;
}

extern "C" void kernel_launch(void* const* d_in, const int* in_sizes, int n_in,
                              void* d_out, int out_size)
{
    const float* data   = (const float*)d_in[0];
    const float* conv_w = (const float*)d_in[1];
    const float* conv_b = (const float*)d_in[2];
    float* out = (float*)d_out;

    conv_hybrid_fused<<<NBLK, 256>>>(data, conv_w, conv_b, out);
}

// round 7
// speedup vs baseline: 1.0577x; 1.0577x over previous
#include <cuda_runtime.h>

#define IMG   64
#define OUTW  61
#define NB    256
#define NBLK  512              // 256 images x 2 half-images
#define NOUT  (OUTW * OUTW)

// Deterministic scratch + completion ticket (rearmed each call -> graph-replayable).
__device__ float4       g_partials4[NBLK / 4];
__device__ unsigned int g_ticket = 0;

__device__ __forceinline__ float fast_sigmoid(float x)
{
    float t;
    asm("tanh.approx.f32 %0, %1;" : "=f"(t) : "f"(0.5f * x));
    return fmaf(0.5f, t, 0.5f);          // sigmoid(x) = 0.5*tanh(x/2) + 0.5
}

__global__ void __launch_bounds__(256) conv_hybrid_fused(
    const float* __restrict__ data,
    const float* __restrict__ conv_w,
    const float* __restrict__ conv_b,
    float* __restrict__ out)
{
    __shared__ float red[8];

    const int t    = threadIdx.x;
    const int lane = t & 31;
    const int wid  = t >> 5;
    const int bid  = blockIdx.x;
    const int b    = bid >> 1;                 // image
    const int s    = bid & 1;                  // half: rows 0..30 / 31..60
    const int nrows  = s ? 30 : 31;
    const int ntasks = nrows * 16;

    // Weights + bias -> registers (uniform broadcast loads, no barrier needed).
    const float4 W0 = __ldg((const float4*)conv_w + 0);
    const float4 W1 = __ldg((const float4*)conv_w + 1);
    const float4 W2 = __ldg((const float4*)conv_w + 2);
    const float4 W3 = __ldg((const float4*)conv_w + 3);
    const float bias = __ldg(conv_b);

    // Two tasks per thread: tau0 = t, tau1 = t + 256. g identical for both.
    const int g  = t & 15;                     // cols 4g..4g+3
    const int r0 = t >> 4;                     // 0..15, always < nrows
    int r1 = (t + 256) >> 4;                   // 16..31
    if (r1 > nrows - 1) r1 = nrows - 1;        // clamp keeps loads in-bounds
    const bool v1 = (t + 256) < ntasks;

    const float* base = data + ((size_t)b << 12) + s * 31 * IMG + (g << 2);
    const float* p0 = base + r0 * IMG;
    const float* p1 = base + r1 * IMG;

    // 8 front-batched LDG.128 (MLP=8, single latency exposure).
    const float4 A0 = *(const float4*)(p0);
    const float4 B0 = *(const float4*)(p0 + IMG);
    const float4 C0 = *(const float4*)(p0 + 2 * IMG);
    const float4 D0 = *(const float4*)(p0 + 3 * IMG);
    const float4 A1 = *(const float4*)(p1);
    const float4 B1 = *(const float4*)(p1 + IMG);
    const float4 C1 = *(const float4*)(p1 + 2 * IMG);
    const float4 D1 = *(const float4*)(p1 + 3 * IMG);

    // Halo cols 4g+4..4g+6 from lane+1 via shuffle; for g==15 (and lane 31)
    // the shuffled values are garbage but feed only acc1..acc3, discarded there.
#define DO_ROW(F, W, a0, a1, a2, a3) do {                                    \
        const float h4 = __shfl_down_sync(0xffffffffu, (F).x, 1);            \
        const float h5 = __shfl_down_sync(0xffffffffu, (F).y, 1);            \
        const float h6 = __shfl_down_sync(0xffffffffu, (F).z, 1);            \
        a0 = fmaf((F).x,(W).x, fmaf((F).y,(W).y, fmaf((F).z,(W).z, fmaf((F).w,(W).w, a0)))); \
        a1 = fmaf((F).y,(W).x, fmaf((F).z,(W).y, fmaf((F).w,(W).z, fmaf(h4,  (W).w, a1)))); \
        a2 = fmaf((F).z,(W).x, fmaf((F).w,(W).y, fmaf(h4,  (W).z, fmaf(h5,  (W).w, a2)))); \
        a3 = fmaf((F).w,(W).x, fmaf(h4,  (W).y, fmaf(h5,  (W).z, fmaf(h6,  (W).w, a3)))); \
    } while (0)

    float x0 = bias, x1 = bias, x2 = bias, x3 = bias;   // task 0
    float y0 = bias, y1 = bias, y2 = bias, y3 = bias;   // task 1
    DO_ROW(A0, W0, x0, x1, x2, x3);
    DO_ROW(B0, W1, x0, x1, x2, x3);
    DO_ROW(C0, W2, x0, x1, x2, x3);
    DO_ROW(D0, W3, x0, x1, x2, x3);
    DO_ROW(A1, W0, y0, y1, y2, y3);
    DO_ROW(B1, W1, y0, y1, y2, y3);
    DO_ROW(C1, W2, y0, y1, y2, y3);
    DO_ROW(D1, W3, y0, y1, y2, y3);
#undef DO_ROW

    // Valid columns: j=4g always (<61); j+1..j+3 valid iff g<15.
    float lsum = fast_sigmoid(x0);
    if (g < 15) lsum += fast_sigmoid(x1) + fast_sigmoid(x2) + fast_sigmoid(x3);
    if (v1) {
        lsum += fast_sigmoid(y0);
        if (g < 15) lsum += fast_sigmoid(y1) + fast_sigmoid(y2) + fast_sigmoid(y3);
    }

    // Deterministic intra-warp tree reduce, then one smem slot per warp.
    #pragma unroll
    for (int o = 16; o; o >>= 1)
        lsum += __shfl_xor_sync(0xffffffffu, lsum, o);
    if (lane == 0) red[wid] = lsum;
    __syncthreads();                            // the ONLY block barrier

    if (wid != 0) return;                       // warps 1..7 done

    // ── Warp 0: per-CTA partial + ticket ──
    float v = (lane < 8) ? red[lane] : 0.0f;
    #pragma unroll
    for (int o = 16; o; o >>= 1)
        v += __shfl_xor_sync(0xffffffffu, v, o);

    unsigned int tk = 0;
    if (lane == 0) {
        ((float*)g_partials4)[bid] = v;
        __threadfence();                        // release partial before ticket
        tk = atomicAdd(&g_ticket, 1u);
    }
    tk = __shfl_sync(0xffffffffu, tk, 0);
    if (tk != NBLK - 1) return;

    // ── Last CTA, warp 0 only: global reduce over 512 partials ──
    if (lane == 0) atomicExch(&g_ticket, 0u);   // rearm for graph replay
    __threadfence();                            // acquire partials

    float acc = 0.0f;
    #pragma unroll
    for (int k = 0; k < 4; k++) {               // fixed order -> deterministic
        const float4 q = g_partials4[lane + k * 32];
        acc += ((q.x + q.y) + (q.z + q.w));
    }
    #pragma unroll
    for (int o = 16; o; o >>= 1)
        acc += __shfl_xor_sync(0xffffffffu, acc, o);

    // Quantum term: the state stays exactly uniform under RX(theta in
    // {0, float32(pi)}) and the CX chain, so qexp = (c^2+s^2)^k - 1 and
    // c^2+s^2 == 1.0f exactly in fp32 -> qexp == 0 for every batch element.
    // Hence out[b] = 0.5 * classical_mean for all b.
    const float r = 0.5f * acc * (1.0f / ((float)NB * (float)NOUT));
    const float4 rv = make_float4(r, r, r, r);
    float4* o4 = (float4*)out;                  // 256 floats = 64 float4
    o4[lane]      = rv;
    o4[lane + 32] = rv;
}

extern "C" void kernel_launch(void* const* d_in, const int* in_sizes, int n_in,
                              void* d_out, int out_size)
{
    const float* data   = (const float*)d_in[0];
    const float* conv_w = (const float*)d_in[1];
    const float* conv_b = (const float*)d_in[2];
    float* out = (float*)d_out;

    conv_hybrid_fused<<<NBLK, 256>>>(data, conv_w, conv_b, out);
}

// round 8
// speedup vs baseline: 1.1379x; 1.0759x over previous
#include <cuda_runtime.h>

#define IMG   64
#define OUTW  61
#define NB    256
#define NBLK  256              // one CTA per image
#define NOUT  (OUTW * OUTW)

// Deterministic scratch + completion ticket (rearmed each call -> graph-replayable).
__device__ float4       g_partials4[NBLK / 4];
__device__ unsigned int g_ticket = 0;

__device__ __forceinline__ float fast_sigmoid(float x)
{
    float t;
    asm("tanh.approx.f32 %0, %1;" : "=f"(t) : "f"(0.5f * x));
    return fmaf(0.5f, t, 0.5f);          // sigmoid(x) = 0.5*tanh(x/2) + 0.5
}

__global__ void __launch_bounds__(256) conv_hybrid_fused(
    const float* __restrict__ data,
    const float* __restrict__ conv_w,
    const float* __restrict__ conv_b,
    float* __restrict__ out)
{
    __shared__ float red[8];

    const int t    = threadIdx.x;
    const int lane = t & 31;
    const int wid  = t >> 5;
    const int b    = blockIdx.x;

    // Thread -> 4x4 output patch: rows r0..r0+3, cols 4g..4g+3.
    const int g  = t & 15;
    const int r0 = (t >> 4) << 2;            // 0,4,...,60

    // Weights + bias -> registers (uniform broadcast loads, no barrier).
    const float4 W0 = __ldg((const float4*)conv_w + 0);
    const float4 W1 = __ldg((const float4*)conv_w + 1);
    const float4 W2 = __ldg((const float4*)conv_w + 2);
    const float4 W3 = __ldg((const float4*)conv_w + 3);
    const float bias = __ldg(conv_b);

    // 14 front-batched LDG.128: 7 input rows x 8 cols (two overlapping float4).
    // Rows clamped at 63 (feeds only invalid outputs); for g==15 the halo
    // float4 aliases the main one (halo cols feed only discarded acc1..acc3).
    const float* img  = data + ((size_t)b << 12) + (g << 2);
    const int    hoff = (g < 15) ? 4 : 0;
    float4 L[7], H[7];
    #pragma unroll
    for (int k = 0; k < 7; k++) {
        int row = r0 + k; if (row > 63) row = 63;
        const float* p = img + row * IMG;
        L[k] = *(const float4*)p;
        H[k] = *(const float4*)(p + hoff);
    }

    float lsum = 0.0f;
    #pragma unroll
    for (int rr = 0; rr < 4; rr++) {
        float a0 = bias, a1 = bias, a2 = bias, a3 = bias;
        #pragma unroll
        for (int dr = 0; dr < 4; dr++) {
            const float4 F = L[rr + dr];
            const float4 X = H[rr + dr];
            const float4 W = (dr == 0) ? W0 : (dr == 1) ? W1 : (dr == 2) ? W2 : W3;
            a0 = fmaf(F.x, W.x, fmaf(F.y, W.y, fmaf(F.z, W.z, fmaf(F.w, W.w, a0))));
            a1 = fmaf(F.y, W.x, fmaf(F.z, W.y, fmaf(F.w, W.z, fmaf(X.x, W.w, a1))));
            a2 = fmaf(F.z, W.x, fmaf(F.w, W.y, fmaf(X.x, W.z, fmaf(X.y, W.w, a2))));
            a3 = fmaf(F.w, W.x, fmaf(X.x, W.y, fmaf(X.y, W.z, fmaf(X.z, W.w, a3))));
        }
        if (r0 + rr < OUTW) {                       // output row valid
            lsum += fast_sigmoid(a0);               // col 4g always < 61
            if (g < 15)                             // cols 4g+1..4g+3
                lsum += fast_sigmoid(a1) + fast_sigmoid(a2) + fast_sigmoid(a3);
        }
    }

    // Deterministic intra-warp tree reduce, then one smem slot per warp.
    #pragma unroll
    for (int o = 16; o; o >>= 1)
        lsum += __shfl_xor_sync(0xffffffffu, lsum, o);
    if (lane == 0) red[wid] = lsum;
    __syncthreads();                                // the ONLY block barrier

    if (wid != 0) return;

    // ── Warp 0: per-CTA partial + ticket ──
    float v = (lane < 8) ? red[lane] : 0.0f;
    #pragma unroll
    for (int o = 16; o; o >>= 1)
        v += __shfl_xor_sync(0xffffffffu, v, o);

    unsigned int tk = 0;
    if (lane == 0) {
        ((float*)g_partials4)[b] = v;
        __threadfence();                            // release partial before ticket
        tk = atomicAdd(&g_ticket, 1u);
    }
    tk = __shfl_sync(0xffffffffu, tk, 0);
    if (tk != NBLK - 1) return;

    // ── Last CTA, warp 0 only: global reduce over 256 partials ──
    if (lane == 0) atomicExch(&g_ticket, 0u);       // rearm for graph replay
    __threadfence();                                // acquire partials

    float acc = 0.0f;
    #pragma unroll
    for (int k = 0; k < 2; k++) {                   // fixed order -> deterministic
        const float4 q = g_partials4[lane + k * 32];
        acc += ((q.x + q.y) + (q.z + q.w));
    }
    #pragma unroll
    for (int o = 16; o; o >>= 1)
        acc += __shfl_xor_sync(0xffffffffu, acc, o);

    // Quantum term: the state stays exactly uniform under RX(theta in
    // {0, float32(pi)}) and the CX chain, so qexp = (c^2+s^2)^k - 1 and
    // c^2+s^2 == 1.0f exactly in fp32 -> qexp == 0 for every batch element.
    // Hence out[b] = 0.5 * classical_mean for all b.
    const float r = 0.5f * acc * (1.0f / ((float)NB * (float)NOUT));
    const float4 rv = make_float4(r, r, r, r);
    float4* o4 = (float4*)out;                      // 256 floats = 64 float4
    o4[lane]      = rv;
    o4[lane + 32] = rv;
}

extern "C" void kernel_launch(void* const* d_in, const int* in_sizes, int n_in,
                              void* d_out, int out_size)
{
    const float* data   = (const float*)d_in[0];
    const float* conv_w = (const float*)d_in[1];
    const float* conv_b = (const float*)d_in[2];
    float* out = (float*)d_out;

    conv_hybrid_fused<<<NBLK, 256>>>(data, conv_w, conv_b, out);
}

// round 10
// speedup vs baseline: 1.2132x; 1.0662x over previous
#include <cuda_runtime.h>

#define IMG   64
#define OUTW  61
#define NB    256
#define NBLK  128              // single wave: 128 CTAs x 512 thr, 2 images/CTA
#define NOUT  (OUTW * OUTW)

// Deterministic scratch + completion ticket (rearmed each call -> graph-replayable).
__device__ float4       g_partials4[NBLK / 4];
__device__ unsigned int g_ticket = 0;

__device__ __forceinline__ float fast_sigmoid(float x)
{
    float t;
    asm("tanh.approx.f32 %0, %1;" : "=f"(t) : "f"(0.5f * x));
    return fmaf(0.5f, t, 0.5f);          // sigmoid(x) = 0.5*tanh(x/2) + 0.5
}

__global__ void __launch_bounds__(512) conv_hybrid_fused(
    const float* __restrict__ data,
    const float* __restrict__ conv_w,
    const float* __restrict__ conv_b,
    float* __restrict__ out)
{
    __shared__ float red[16];

    const int t     = threadIdx.x;
    const int lane  = t & 31;
    const int wid   = t >> 5;                 // 0..15
    const int local = t & 255;
    const int b     = (blockIdx.x << 1) | (t >> 8);   // image for this half-block

    // Thread -> 4x4 output patch: rows r0..r0+3, cols 4g..4g+3.
    const int g  = local & 15;
    const int r0 = (local >> 4) << 2;         // 0,4,...,60

    // Weights + bias -> registers (uniform broadcast loads, no barrier).
    const float4 W0 = __ldg((const float4*)conv_w + 0);
    const float4 W1 = __ldg((const float4*)conv_w + 1);
    const float4 W2 = __ldg((const float4*)conv_w + 2);
    const float4 W3 = __ldg((const float4*)conv_w + 3);
    const float bias = __ldg(conv_b);

    // 14 front-batched LDG.128: 7 input rows x 8 cols (two overlapping float4).
    // Rows clamped at 63 (feed only invalid outputs); for g==15 the halo
    // float4 aliases the main one (halo cols feed only discarded acc1..acc3).
    const float* img  = data + ((size_t)b << 12) + (g << 2);
    const int    hoff = (g < 15) ? 4 : 0;
    float4 L[7], H[7];
    #pragma unroll
    for (int k = 0; k < 7; k++) {
        int row = r0 + k; if (row > 63) row = 63;
        const float* p = img + row * IMG;
        L[k] = *(const float4*)p;
        H[k] = *(const float4*)(p + hoff);
    }

    float lsum = 0.0f;
    #pragma unroll
    for (int rr = 0; rr < 4; rr++) {
        float a0 = bias, a1 = bias, a2 = bias, a3 = bias;
        #pragma unroll
        for (int dr = 0; dr < 4; dr++) {
            const float4 F = L[rr + dr];
            const float4 X = H[rr + dr];
            const float4 W = (dr == 0) ? W0 : (dr == 1) ? W1 : (dr == 2) ? W2 : W3;
            a0 = fmaf(F.x, W.x, fmaf(F.y, W.y, fmaf(F.z, W.z, fmaf(F.w, W.w, a0))));
            a1 = fmaf(F.y, W.x, fmaf(F.z, W.y, fmaf(F.w, W.z, fmaf(X.x, W.w, a1))));
            a2 = fmaf(F.z, W.x, fmaf(F.w, W.y, fmaf(X.x, W.z, fmaf(X.y, W.w, a2))));
            a3 = fmaf(F.w, W.x, fmaf(X.x, W.y, fmaf(X.y, W.z, fmaf(X.z, W.w, a3))));
        }
        if (r0 + rr < OUTW) {                       // output row valid
            lsum += fast_sigmoid(a0);               // col 4g always < 61
            if (g < 15)                             // cols 4g+1..4g+3
                lsum += fast_sigmoid(a1) + fast_sigmoid(a2) + fast_sigmoid(a3);
        }
    }

    // Deterministic intra-warp tree reduce, then one smem slot per warp.
    #pragma unroll
    for (int o = 16; o; o >>= 1)
        lsum += __shfl_xor_sync(0xffffffffu, lsum, o);
    if (lane == 0) red[wid] = lsum;
    __syncthreads();                                // the ONLY block barrier

    if (wid != 0) return;

    // ── Warp 0: per-CTA partial (both images) + ticket ──
    float v = (lane < 16) ? red[lane] : 0.0f;
    #pragma unroll
    for (int o = 16; o; o >>= 1)
        v += __shfl_xor_sync(0xffffffffu, v, o);

    unsigned int tk = 0;
    if (lane == 0) {
        ((float*)g_partials4)[blockIdx.x] = v;
        __threadfence();                            // release partial before ticket
        tk = atomicAdd(&g_ticket, 1u);
    }
    tk = __shfl_sync(0xffffffffu, tk, 0);
    if (tk != NBLK - 1) return;

    // ── Last CTA, warp 0 only: global reduce over 128 partials ──
    if (lane == 0) atomicExch(&g_ticket, 0u);       // rearm for graph replay
    __threadfence();                                // acquire partials

    const float4 q = g_partials4[lane];             // 32 x float4 = 128, fixed order
    float acc = (q.x + q.y) + (q.z + q.w);
    #pragma unroll
    for (int o = 16; o; o >>= 1)
        acc += __shfl_xor_sync(0xffffffffu, acc, o);

    // Quantum term: the state stays exactly uniform under RX(theta in
    // {0, float32(pi)}) and the CX chain, so qexp = (c^2+s^2)^k - 1 and
    // c^2+s^2 == 1.0f exactly in fp32 -> qexp == 0 for every batch element.
    // Hence out[b] = 0.5 * classical_mean for all b.
    const float r = 0.5f * acc * (1.0f / ((float)NB * (float)NOUT));
    const float4 rv = make_float4(r, r, r, r);
    float4* o4 = (float4*)out;                      // 256 floats = 64 float4
    o4[lane]      = rv;
    o4[lane + 32] = rv;
}

extern "C" void kernel_launch(void* const* d_in, const int* in_sizes, int n_in,
                              void* d_out, int out_size)
{
    const float* data   = (const float*)d_in[0];
    const float* conv_w = (const float*)d_in[1];
    const float* conv_b = (const float*)d_in[2];
    float* out = (float*)d_out;

    conv_hybrid_fused<<<NBLK, 512>>>(data, conv_w, conv_b, out);
}